// round 1
// baseline (speedup 1.0000x reference)
#include <cuda_runtime.h>
#include <cuda_bf16.h>

// Problem shape (fixed by the dataset): B=16, n=4096 (s=64, g=32, P=2), D=1024.
#define B_SZ   16
#define N_TOK  4096
#define D_DIM  1024
#define NTOK_TOTAL (B_SZ * N_TOK)   // 65536

#define BM 128
#define BN 128
#define BK 16

// Scratch: per-token logits (allocation-free rule -> __device__ global)
__device__ float g_logits[NTOK_TOTAL];

// ---------------------------------------------------------------------------
// Kernel A: fused logits GEMM.
// Each block handles 128 tokens; loops over all 1024 hidden features in
// chunks of 128, computing h = relu(x@W1 + b1) tile-by-tile and reducing
// against w2 on the fly. Only the scalar logit per token hits memory.
// ---------------------------------------------------------------------------
__global__ __launch_bounds__(256, 2)
void logits_kernel(const float* __restrict__ x,
                   const float* __restrict__ W1,
                   const float* __restrict__ b1,
                   const float* __restrict__ W2,
                   const float* __restrict__ b2)
{
    __shared__ float As[BK][BM];   // x tile, k-major
    __shared__ float Bs[BK][BN];   // W1 tile, k-major
    __shared__ float red[16][BM];  // cross-thread logit reduction

    const int tid = threadIdx.x;
    const int ty  = tid >> 4;      // 0..15  (token-row group)
    const int tx  = tid & 15;      // 0..15  (feature-col group)
    const int m0  = blockIdx.x * BM;

    // global-load assignments
    const int a_m  = tid >> 1;             // 0..127
    const int a_k  = (tid & 1) * 8;        // 0 or 8
    const int b_k  = tid >> 5;             // 0..7 (also +8)
    const int b_e  = (tid & 31) * 4;       // 0..124

    float s[8];
    #pragma unroll
    for (int i = 0; i < 8; i++) s[i] = 0.f;

    const float* xrow = x + (size_t)(m0 + a_m) * D_DIM;

    for (int nc = 0; nc < D_DIM / BN; nc++) {
        const int e0 = nc * BN;
        float acc[8][8];
        #pragma unroll
        for (int i = 0; i < 8; i++)
            #pragma unroll
            for (int j = 0; j < 8; j++) acc[i][j] = 0.f;

        for (int kt = 0; kt < D_DIM / BK; kt++) {
            const int k0 = kt * BK;
            // load x tile (transposed into k-major)
            float4 av0 = *(const float4*)(xrow + k0 + a_k);
            float4 av1 = *(const float4*)(xrow + k0 + a_k + 4);
            As[a_k + 0][a_m] = av0.x; As[a_k + 1][a_m] = av0.y;
            As[a_k + 2][a_m] = av0.z; As[a_k + 3][a_m] = av0.w;
            As[a_k + 4][a_m] = av1.x; As[a_k + 5][a_m] = av1.y;
            As[a_k + 6][a_m] = av1.z; As[a_k + 7][a_m] = av1.w;
            // load W1 tile (already k-major in gmem)
            float4 bv0 = *(const float4*)(W1 + (size_t)(k0 + b_k) * D_DIM + e0 + b_e);
            float4 bv1 = *(const float4*)(W1 + (size_t)(k0 + b_k + 8) * D_DIM + e0 + b_e);
            *(float4*)&Bs[b_k][b_e]     = bv0;
            *(float4*)&Bs[b_k + 8][b_e] = bv1;
            __syncthreads();

            #pragma unroll
            for (int kk = 0; kk < BK; kk++) {
                float4 a0 = *(const float4*)&As[kk][ty * 8];
                float4 a1 = *(const float4*)&As[kk][ty * 8 + 4];
                float4 c0 = *(const float4*)&Bs[kk][tx * 8];
                float4 c1 = *(const float4*)&Bs[kk][tx * 8 + 4];
                float ra[8] = {a0.x, a0.y, a0.z, a0.w, a1.x, a1.y, a1.z, a1.w};
                float rb[8] = {c0.x, c0.y, c0.z, c0.w, c1.x, c1.y, c1.z, c1.w};
                #pragma unroll
                for (int i = 0; i < 8; i++)
                    #pragma unroll
                    for (int j = 0; j < 8; j++)
                        acc[i][j] = fmaf(ra[i], rb[j], acc[i][j]);
            }
            __syncthreads();
        }

        // epilogue: bias + relu + reduce against w2 into per-token partials
        #pragma unroll
        for (int j = 0; j < 8; j++) {
            const int e = e0 + tx * 8 + j;
            const float bb = b1[e];
            const float w  = W2[e];          // W2 is [D,1]
            #pragma unroll
            for (int i = 0; i < 8; i++) {
                float h = fmaxf(acc[i][j] + bb, 0.f);
                s[i] = fmaf(h, w, s[i]);
            }
        }
    }

    // reduce the 16 feature-column groups per token
    #pragma unroll
    for (int i = 0; i < 8; i++) red[tx][ty * 8 + i] = s[i];
    __syncthreads();
    if (tid < BM) {
        float tot = 0.f;
        #pragma unroll
        for (int t = 0; t < 16; t++) tot += red[t][tid];
        g_logits[(size_t)m0 + tid] = tot + b2[0];
    }
}

// ---------------------------------------------------------------------------
// Kernel B: 2x2 window softmax + weighted sum.
// One block per (batch, region). 256 threads x float4 covers D=1024.
// Region r = i*32 + j; window tokens: (2i+p)*64 + (2j+q), k = p*2+q.
// ---------------------------------------------------------------------------
__global__ __launch_bounds__(256)
void pool_kernel(const float* __restrict__ x, float* __restrict__ out)
{
    const int br = blockIdx.x;          // b*1024 + r
    const int b  = br >> 10;
    const int r  = br & 1023;
    const int i  = r >> 5;
    const int j  = r & 31;
    const int t00 = (i * 2) * 64 + (j * 2);
    const int t01 = t00 + 1;
    const int t10 = t00 + 64;
    const int t11 = t00 + 65;

    const float* lg = g_logits + (size_t)b * N_TOK;
    float l0 = lg[t00], l1 = lg[t01], l2 = lg[t10], l3 = lg[t11];
    float mx = fmaxf(fmaxf(l0, l1), fmaxf(l2, l3));
    float e0 = __expf(l0 - mx), e1 = __expf(l1 - mx);
    float e2 = __expf(l2 - mx), e3 = __expf(l3 - mx);
    float inv = 1.f / (e0 + e1 + e2 + e3);
    float a0 = e0 * inv, a1 = e1 * inv, a2 = e2 * inv, a3 = e3 * inv;

    const size_t xb = (size_t)b * N_TOK * D_DIM;
    const float4* x0 = (const float4*)(x + xb + (size_t)t00 * D_DIM);
    const float4* x1 = (const float4*)(x + xb + (size_t)t01 * D_DIM);
    const float4* x2 = (const float4*)(x + xb + (size_t)t10 * D_DIM);
    const float4* x3 = (const float4*)(x + xb + (size_t)t11 * D_DIM);
    float4* o = (float4*)(out + (size_t)br * D_DIM);

    const int d = threadIdx.x;          // one float4 each (256*4 = 1024)
    float4 v0 = x0[d], v1 = x1[d], v2 = x2[d], v3 = x3[d];
    float4 ov;
    ov.x = a0 * v0.x + a1 * v1.x + a2 * v2.x + a3 * v3.x;
    ov.y = a0 * v0.y + a1 * v1.y + a2 * v2.y + a3 * v3.y;
    ov.z = a0 * v0.z + a1 * v1.z + a2 * v2.z + a3 * v3.z;
    ov.w = a0 * v0.w + a1 * v1.w + a2 * v2.w + a3 * v3.w;
    o[d] = ov;
}

// ---------------------------------------------------------------------------
extern "C" void kernel_launch(void* const* d_in, const int* in_sizes, int n_in,
                              void* d_out, int out_size)
{
    const float* x  = (const float*)d_in[0];
    const float* W1 = (const float*)d_in[1];
    const float* b1 = (const float*)d_in[2];
    const float* W2 = (const float*)d_in[3];
    const float* b2 = (const float*)d_in[4];
    float* out = (float*)d_out;

    logits_kernel<<<NTOK_TOTAL / BM, 256>>>(x, W1, b1, W2, b2);
    pool_kernel<<<B_SZ * (N_TOK / 4), 256>>>(x, out);
}

// round 4
// speedup vs baseline: 1.6404x; 1.6404x over previous
#include <cuda_runtime.h>
#include <cuda_bf16.h>
#include <mma.h>
#include <cstdint>

using namespace nvcuda;

// Shape: B=16, n=4096, D=1024. Tokens = 65536.
#define B_SZ   16
#define N_TOK  4096
#define D_DIM  1024
#define NTOK_TOTAL (B_SZ * N_TOK)

#define NCHUNKS 8          // 1024 / BN
#define BM 128
#define BN 128
#define BK 32
#define XPAD 40            // bf16 elems per x-tile row in smem
#define WPAD 136           // bf16 elems per w-tile row in smem
#define EPAD 132           // f32 elems per epilogue row in smem

// Scratch (__device__ globals: allocation-free rule)
__device__ float g_part[NCHUNKS][NTOK_TOTAL];          // partial logits per n-chunk
__device__ __nv_bfloat16 g_Whi[D_DIM * D_DIM];         // bf16 hi of W1 [k][e]
__device__ __nv_bfloat16 g_Wlo[D_DIM * D_DIM];         // bf16 lo of W1 [k][e]

// ---------------------------------------------------------------------------
// Kernel 0: split W1 into bf16 hi/lo (native [k,e] layout; no transpose).
// ---------------------------------------------------------------------------
__global__ __launch_bounds__(256)
void prep_w_kernel(const float* __restrict__ W1)
{
    const int base = blockIdx.x * 1024 + threadIdx.x * 4;
    #pragma unroll
    for (int u = 0; u < 4; u++) {
        const int i = base + u;
        float w = W1[i];
        __nv_bfloat16 hi = __float2bfloat16(w);
        g_Whi[i] = hi;
        g_Wlo[i] = __float2bfloat16(w - __bfloat162float(hi));
    }
}

// ---------------------------------------------------------------------------
// Kernel A: bf16x3 wmma logits GEMM.
// Grid (8, 512): blockIdx.x = n-chunk (128 hidden feats), blockIdx.y = m-tile
// (128 tokens). n fastest -> 8 co-resident blocks share each x tile via L2.
// Per block: acc[128x128] in wmma accumulators (8 warps, warp tile 32x64),
// K=1024 streamed in 32 stages of BK=32 with register-staged double buffer.
// Epilogue: relu(acc + b1) . w2 -> per-token partial logit to g_part.
// ---------------------------------------------------------------------------

// smem layout (bytes):
//   stage s (s=0,1) at s*STAGE_B:
//     xh: [128][XPAD] bf16   off 0      (10240)
//     xl: [128][XPAD] bf16   off 10240  (10240)
//     wh: [32][WPAD]  bf16   off 20480  (8704)
//     wl: [32][WPAD]  bf16   off 29184  (8704)
//   epilogue ep: [128][EPAD] f32 aliases offset 0 (67584 < 2*STAGE_B)
//   s_b1[128] f32 at 75776, s_w2[128] f32 at 76288; total 76800
#define STAGE_B 37888
#define SM_B1   75776
#define SM_W2   76288
#define SMEM_TOTAL 76800

__global__ __launch_bounds__(256)
void logits_wmma_kernel(const float* __restrict__ x,
                        const float* __restrict__ b1,
                        const float* __restrict__ W2)
{
    extern __shared__ char smem[];
    const int tid = threadIdx.x;
    const int wid = tid >> 5;
    const int n0  = blockIdx.x * BN;
    const int m0  = blockIdx.y * BM;

    float* s_b1 = (float*)(smem + SM_B1);
    float* s_w2 = (float*)(smem + SM_W2);
    if (tid < 128) { s_b1[tid] = b1[n0 + tid]; s_w2[tid] = W2[n0 + tid]; }

    // loader assignments
    // x: 128 rows x 32 cols f32 = 1024 float4 slots; 4 per thread
    const int xs0 = tid * 4;
    // w: 32 rows x 128 cols bf16 = 512 uint4 slots per matrix; 2 per thread
    const int ws0 = tid * 2;

    float4 xr[4];
    uint4  wrh[2], wrl[2];

    auto load_regs = [&](int kt) {
        const int k0 = kt * BK;
        #pragma unroll
        for (int q = 0; q < 4; q++) {
            const int s = xs0 + q;
            const int r = s >> 3, c4 = s & 7;
            xr[q] = *(const float4*)(x + (size_t)(m0 + r) * D_DIM + k0 + c4 * 4);
        }
        #pragma unroll
        for (int q = 0; q < 2; q++) {
            const int s = ws0 + q;
            const int r = s >> 4, c8 = s & 15;
            const size_t a = (size_t)(k0 + r) * D_DIM + n0 + c8 * 8;
            wrh[q] = *(const uint4*)(g_Whi + a);
            wrl[q] = *(const uint4*)(g_Wlo + a);
        }
    };

    auto store_stage = [&](int buf) {
        char* sb = smem + buf * STAGE_B;
        __nv_bfloat16 (*xh)[XPAD] = (__nv_bfloat16(*)[XPAD])(sb);
        __nv_bfloat16 (*xl)[XPAD] = (__nv_bfloat16(*)[XPAD])(sb + 10240);
        __nv_bfloat16 (*wh)[WPAD] = (__nv_bfloat16(*)[WPAD])(sb + 20480);
        __nv_bfloat16 (*wl)[WPAD] = (__nv_bfloat16(*)[WPAD])(sb + 29184);
        #pragma unroll
        for (int q = 0; q < 4; q++) {
            const int s = xs0 + q;
            const int r = s >> 3, c = (s & 7) * 4;
            const float f[4] = {xr[q].x, xr[q].y, xr[q].z, xr[q].w};
            #pragma unroll
            for (int u = 0; u < 2; u++) {
                __nv_bfloat16 h0 = __float2bfloat16(f[2*u]);
                __nv_bfloat16 h1 = __float2bfloat16(f[2*u+1]);
                __nv_bfloat16 l0 = __float2bfloat16(f[2*u]   - __bfloat162float(h0));
                __nv_bfloat16 l1 = __float2bfloat16(f[2*u+1] - __bfloat162float(h1));
                *(__nv_bfloat162*)&xh[r][c + 2*u] = __halves2bfloat162(h0, h1);
                *(__nv_bfloat162*)&xl[r][c + 2*u] = __halves2bfloat162(l0, l1);
            }
        }
        #pragma unroll
        for (int q = 0; q < 2; q++) {
            const int s = ws0 + q;
            const int r = s >> 4, c = (s & 15) * 8;
            *(uint4*)&wh[r][c] = wrh[q];
            *(uint4*)&wl[r][c] = wrl[q];
        }
    };

    // warp tile: 32 rows x 64 cols; warp grid 4(m) x 2(n)
    const int wm = wid & 3;
    const int wn = wid >> 2;

    wmma::fragment<wmma::accumulator, 16, 16, 16, float> acc[2][4];
    #pragma unroll
    for (int i = 0; i < 2; i++)
        #pragma unroll
        for (int j = 0; j < 4; j++) wmma::fill_fragment(acc[i][j], 0.f);

    load_regs(0);
    store_stage(0);
    __syncthreads();

    for (int kt = 0; kt < D_DIM / BK; kt++) {
        const int cur = kt & 1;
        if (kt + 1 < D_DIM / BK) load_regs(kt + 1);

        char* sb = smem + cur * STAGE_B;
        const __nv_bfloat16 (*xh)[XPAD] = (const __nv_bfloat16(*)[XPAD])(sb);
        const __nv_bfloat16 (*xl)[XPAD] = (const __nv_bfloat16(*)[XPAD])(sb + 10240);
        const __nv_bfloat16 (*wh)[WPAD] = (const __nv_bfloat16(*)[WPAD])(sb + 20480);
        const __nv_bfloat16 (*wl)[WPAD] = (const __nv_bfloat16(*)[WPAD])(sb + 29184);

        #pragma unroll
        for (int kk = 0; kk < BK; kk += 16) {
            wmma::fragment<wmma::matrix_a, 16, 16, 16, __nv_bfloat16, wmma::row_major> ah[2], al[2];
            #pragma unroll
            for (int i = 0; i < 2; i++) {
                wmma::load_matrix_sync(ah[i], &xh[wm * 32 + i * 16][kk], XPAD);
                wmma::load_matrix_sync(al[i], &xl[wm * 32 + i * 16][kk], XPAD);
            }
            #pragma unroll
            for (int j = 0; j < 4; j++) {
                wmma::fragment<wmma::matrix_b, 16, 16, 16, __nv_bfloat16, wmma::row_major> bh, bl;
                wmma::load_matrix_sync(bh, &wh[kk][wn * 64 + j * 16], WPAD);
                wmma::load_matrix_sync(bl, &wl[kk][wn * 64 + j * 16], WPAD);
                #pragma unroll
                for (int i = 0; i < 2; i++) {
                    wmma::mma_sync(acc[i][j], ah[i], bh, acc[i][j]);
                    wmma::mma_sync(acc[i][j], ah[i], bl, acc[i][j]);
                    wmma::mma_sync(acc[i][j], al[i], bh, acc[i][j]);
                }
            }
        }

        if (kt + 1 < D_DIM / BK) store_stage(cur ^ 1);
        __syncthreads();
    }

    // epilogue: dump acc to smem (aliases stage buffers), then reduce
    float (*ep)[EPAD] = (float(*)[EPAD])smem;
    #pragma unroll
    for (int i = 0; i < 2; i++)
        #pragma unroll
        for (int j = 0; j < 4; j++)
            wmma::store_matrix_sync(&ep[wm * 32 + i * 16][wn * 64 + j * 16],
                                    acc[i][j], EPAD, wmma::mem_row_major);
    __syncthreads();

    const int row  = tid >> 1;
    const int half = tid & 1;
    float v = 0.f;
    #pragma unroll 8
    for (int c = 0; c < 64; c++) {
        const int e = half * 64 + c;
        float t = ep[row][e] + s_b1[e];
        t = fmaxf(t, 0.f);
        v = fmaf(t, s_w2[e], v);
    }
    v += __shfl_xor_sync(0xffffffffu, v, 1);
    if (half == 0) g_part[blockIdx.x][(size_t)m0 + row] = v;
}

// ---------------------------------------------------------------------------
// Kernel B: sum partial logits, 2x2 window softmax + weighted sum.
// (b2 omitted: softmax is shift-invariant.)
// ---------------------------------------------------------------------------
__global__ __launch_bounds__(256)
void pool_kernel(const float* __restrict__ x, float* __restrict__ out)
{
    const int br = blockIdx.x;
    const int b  = br >> 10;
    const int r  = br & 1023;
    const int i  = r >> 5;
    const int j  = r & 31;
    const int t00 = (i * 2) * 64 + (j * 2);
    const int tok[4] = {t00, t00 + 1, t00 + 64, t00 + 65};

    float l[4];
    #pragma unroll
    for (int k = 0; k < 4; k++) {
        const int t = b * N_TOK + tok[k];
        float s = 0.f;
        #pragma unroll
        for (int c = 0; c < NCHUNKS; c++) s += g_part[c][t];
        l[k] = s;
    }
    float mx = fmaxf(fmaxf(l[0], l[1]), fmaxf(l[2], l[3]));
    float e0 = __expf(l[0] - mx), e1 = __expf(l[1] - mx);
    float e2 = __expf(l[2] - mx), e3 = __expf(l[3] - mx);
    float inv = 1.f / (e0 + e1 + e2 + e3);
    float a0 = e0 * inv, a1 = e1 * inv, a2 = e2 * inv, a3 = e3 * inv;

    const size_t xb = (size_t)b * N_TOK * D_DIM;
    const float4* x0 = (const float4*)(x + xb + (size_t)tok[0] * D_DIM);
    const float4* x1 = (const float4*)(x + xb + (size_t)tok[1] * D_DIM);
    const float4* x2 = (const float4*)(x + xb + (size_t)tok[2] * D_DIM);
    const float4* x3 = (const float4*)(x + xb + (size_t)tok[3] * D_DIM);
    float4* o = (float4*)(out + (size_t)br * D_DIM);

    const int d = threadIdx.x;
    float4 v0 = x0[d], v1 = x1[d], v2 = x2[d], v3 = x3[d];
    float4 ov;
    ov.x = a0 * v0.x + a1 * v1.x + a2 * v2.x + a3 * v3.x;
    ov.y = a0 * v0.y + a1 * v1.y + a2 * v2.y + a3 * v3.y;
    ov.z = a0 * v0.z + a1 * v1.z + a2 * v2.z + a3 * v3.z;
    ov.w = a0 * v0.w + a1 * v1.w + a2 * v2.w + a3 * v3.w;
    o[d] = ov;
}

// ---------------------------------------------------------------------------
extern "C" void kernel_launch(void* const* d_in, const int* in_sizes, int n_in,
                              void* d_out, int out_size)
{
    const float* x  = (const float*)d_in[0];
    const float* W1 = (const float*)d_in[1];
    const float* b1 = (const float*)d_in[2];
    const float* W2 = (const float*)d_in[3];
    float* out = (float*)d_out;

    cudaFuncSetAttribute(logits_wmma_kernel,
                         cudaFuncAttributeMaxDynamicSharedMemorySize, SMEM_TOTAL);

    prep_w_kernel<<<D_DIM, 256>>>(W1);
    logits_wmma_kernel<<<dim3(NCHUNKS, NTOK_TOTAL / BM), 256, SMEM_TOTAL>>>(x, b1, W2);
    pool_kernel<<<B_SZ * (N_TOK / 4), 256>>>(x, out);
}

// round 5
// speedup vs baseline: 2.0689x; 1.2612x over previous
#include <cuda_runtime.h>
#include <cuda_bf16.h>
#include <mma.h>
#include <cstdint>

using namespace nvcuda;

// Shape: B=16, n=4096, D=1024. Tokens = 65536.
#define B_SZ   16
#define N_TOK  4096
#define D_DIM  1024
#define NTOK_TOTAL (B_SZ * N_TOK)

#define NCHUNKS 4          // 1024 / BN
#define BM 128
#define BN 256
#define BK 32
#define KSTEPS (D_DIM / BK)   // 32

#define XPAD 40            // bf16 elems per x-row in smem (32 + 8 pad)
#define WPAD 264           // bf16 elems per w-row in smem (256 + 8 pad)
#define EPAD 260           // f32 elems per epilogue row

// Scratch (__device__ globals: allocation-free rule)
__device__ float g_part[NCHUNKS][NTOK_TOTAL];
__device__ __nv_bfloat16 g_xh[(size_t)NTOK_TOTAL * D_DIM];
__device__ __nv_bfloat16 g_xl[(size_t)NTOK_TOTAL * D_DIM];
__device__ __nv_bfloat16 g_Whi[D_DIM * D_DIM];
__device__ __nv_bfloat16 g_Wlo[D_DIM * D_DIM];

// smem layout (bytes)
#define ST_XH 0
#define ST_XL 10240
#define ST_WH 20480
#define ST_WL 37376
#define STAGE_B 54272
#define NSLOT 3
#define SM_B1 (NSLOT * STAGE_B)          // 162816, 256 f32
#define SM_W2 (SM_B1 + 1024)
#define SMEM_TOTAL (SM_W2 + 1024)        // 164864

__device__ __forceinline__ uint32_t smem_u32(const void* p) {
    uint32_t a;
    asm("{ .reg .u64 t; cvta.to.shared.u64 t, %1; cvt.u32.u64 %0, t; }" : "=r"(a) : "l"(p));
    return a;
}
#define CP16(dst, src) \
    asm volatile("cp.async.cg.shared.global [%0], [%1], 16;" :: "r"(dst), "l"(src) : "memory")
#define CP_COMMIT() asm volatile("cp.async.commit_group;" ::: "memory")
#define CP_WAIT(n)  asm volatile("cp.async.wait_group %0;" :: "n"(n) : "memory")

// ---------------------------------------------------------------------------
// Prep: split x and W1 into bf16 hi/lo.
// ---------------------------------------------------------------------------
__global__ __launch_bounds__(256)
void prep_x_kernel(const float* __restrict__ x)
{
    const size_t i4 = (size_t)blockIdx.x * 256 + threadIdx.x;   // float4 index
    float4 v = ((const float4*)x)[i4];
    const float f[4] = {v.x, v.y, v.z, v.w};
    __nv_bfloat16 h[4], l[4];
    #pragma unroll
    for (int u = 0; u < 4; u++) {
        h[u] = __float2bfloat16(f[u]);
        l[u] = __float2bfloat16(f[u] - __bfloat162float(h[u]));
    }
    ((__nv_bfloat162*)g_xh)[i4 * 2]     = __halves2bfloat162(h[0], h[1]);
    ((__nv_bfloat162*)g_xh)[i4 * 2 + 1] = __halves2bfloat162(h[2], h[3]);
    ((__nv_bfloat162*)g_xl)[i4 * 2]     = __halves2bfloat162(l[0], l[1]);
    ((__nv_bfloat162*)g_xl)[i4 * 2 + 1] = __halves2bfloat162(l[2], l[3]);
}

__global__ __launch_bounds__(256)
void prep_w_kernel(const float* __restrict__ W1)
{
    const int base = blockIdx.x * 1024 + threadIdx.x * 4;
    #pragma unroll
    for (int u = 0; u < 4; u++) {
        const int i = base + u;
        float w = W1[i];
        __nv_bfloat16 hi = __float2bfloat16(w);
        g_Whi[i] = hi;
        g_Wlo[i] = __float2bfloat16(w - __bfloat162float(hi));
    }
}

// ---------------------------------------------------------------------------
// Kernel A: bf16x3 wmma logits GEMM, cp.async pipelined.
// Grid (4, 512): x = n-chunk (256 feats), y = m-tile (128 tokens).
// 8 warps, warp tile 64x64 (2m x 4n). K streamed in 32 stages of BK=32,
// 3 smem slots, pipeline depth 2.
// ---------------------------------------------------------------------------
__global__ __launch_bounds__(256, 1)
void logits_wmma_kernel(const float* __restrict__ b1,
                        const float* __restrict__ W2)
{
    extern __shared__ char smem[];
    const uint32_t sb = smem_u32(smem);
    const int tid = threadIdx.x;
    const int wid = tid >> 5;
    const int n0  = blockIdx.x * BN;
    const int m0  = blockIdx.y * BM;

    float* s_b1 = (float*)(smem + SM_B1);
    float* s_w2 = (float*)(smem + SM_W2);
    if (tid < 256) { s_b1[tid] = b1[n0 + tid]; s_w2[tid] = W2[n0 + tid]; }

    // per-thread cp.async assignments
    const int xrow = tid >> 1;                  // 0..127
    const int xcc  = (tid & 1) * 2;             // chunk col (16B units), 4 per row
    const size_t xg0 = (size_t)(m0 + xrow) * D_DIM + xcc * 8;
    const uint32_t xs0 = xrow * (XPAD * 2) + xcc * 16;

    auto issue_stage = [&](int kt, int slot) {
        const int k0 = kt * BK;
        const uint32_t s = sb + slot * STAGE_B;
        #pragma unroll
        for (int u = 0; u < 2; u++) {
            CP16(s + ST_XH + xs0 + u * 16, g_xh + xg0 + k0 + u * 8);
            CP16(s + ST_XL + xs0 + u * 16, g_xl + xg0 + k0 + u * 8);
        }
        #pragma unroll
        for (int u = 0; u < 4; u++) {
            const int c  = tid * 4 + u;         // 0..1023
            const int r  = c >> 5;              // 0..31 (k row)
            const int cc = c & 31;              // 16B chunk in row
            const size_t g = (size_t)(k0 + r) * D_DIM + n0 + cc * 8;
            const uint32_t so = r * (WPAD * 2) + cc * 16;
            CP16(s + ST_WH + so, g_Whi + g);
            CP16(s + ST_WL + so, g_Wlo + g);
        }
        CP_COMMIT();
    };

    // warp tile: wm in {0,1} (64 rows), wn in {0..3} (64 cols)
    const int wm = wid & 1;
    const int wn = wid >> 1;

    wmma::fragment<wmma::accumulator, 16, 16, 16, float> acc[4][4];
    #pragma unroll
    for (int i = 0; i < 4; i++)
        #pragma unroll
        for (int j = 0; j < 4; j++) wmma::fill_fragment(acc[i][j], 0.f);

    issue_stage(0, 0);
    issue_stage(1, 1);

    #pragma unroll 2
    for (int kt = 0; kt < KSTEPS; kt++) {
        CP_WAIT(1);
        __syncthreads();
        if (kt + 2 < KSTEPS) issue_stage(kt + 2, (kt + 2) % NSLOT);
        else                 CP_COMMIT();

        const char* s = smem + (kt % NSLOT) * STAGE_B;
        const __nv_bfloat16 (*xh)[XPAD] = (const __nv_bfloat16(*)[XPAD])(s + ST_XH);
        const __nv_bfloat16 (*xl)[XPAD] = (const __nv_bfloat16(*)[XPAD])(s + ST_XL);
        const __nv_bfloat16 (*wh)[WPAD] = (const __nv_bfloat16(*)[WPAD])(s + ST_WH);
        const __nv_bfloat16 (*wl)[WPAD] = (const __nv_bfloat16(*)[WPAD])(s + ST_WL);

        #pragma unroll
        for (int kk = 0; kk < BK; kk += 16) {
            wmma::fragment<wmma::matrix_a, 16, 16, 16, __nv_bfloat16, wmma::row_major> ah[4], al[4];
            #pragma unroll
            for (int i = 0; i < 4; i++) {
                wmma::load_matrix_sync(ah[i], &xh[wm * 64 + i * 16][kk], XPAD);
                wmma::load_matrix_sync(al[i], &xl[wm * 64 + i * 16][kk], XPAD);
            }
            #pragma unroll
            for (int j = 0; j < 4; j++) {
                wmma::fragment<wmma::matrix_b, 16, 16, 16, __nv_bfloat16, wmma::row_major> bh, bl;
                wmma::load_matrix_sync(bh, &wh[kk][wn * 64 + j * 16], WPAD);
                wmma::load_matrix_sync(bl, &wl[kk][wn * 64 + j * 16], WPAD);
                #pragma unroll
                for (int i = 0; i < 4; i++) {
                    wmma::mma_sync(acc[i][j], ah[i], bh, acc[i][j]);
                    wmma::mma_sync(acc[i][j], ah[i], bl, acc[i][j]);
                    wmma::mma_sync(acc[i][j], al[i], bh, acc[i][j]);
                }
            }
        }
        __syncthreads();
    }

    // epilogue: acc -> smem (aliases stage slots), reduce against b1/w2
    CP_WAIT(0);
    __syncthreads();
    float (*ep)[EPAD] = (float(*)[EPAD])smem;
    #pragma unroll
    for (int i = 0; i < 4; i++)
        #pragma unroll
        for (int j = 0; j < 4; j++)
            wmma::store_matrix_sync(&ep[wm * 64 + i * 16][wn * 64 + j * 16],
                                    acc[i][j], EPAD, wmma::mem_row_major);
    __syncthreads();

    const int row  = tid >> 1;
    const int half = tid & 1;
    float v = 0.f;
    #pragma unroll 8
    for (int c = 0; c < 128; c++) {
        const int e = half * 128 + c;
        float t = ep[row][e] + s_b1[e];
        t = fmaxf(t, 0.f);
        v = fmaf(t, s_w2[e], v);
    }
    v += __shfl_xor_sync(0xffffffffu, v, 1);
    if (half == 0) g_part[blockIdx.x][(size_t)m0 + row] = v;
}

// ---------------------------------------------------------------------------
// Kernel B: sum partials, 2x2 window softmax + weighted sum. (b2 shift-inv.)
// ---------------------------------------------------------------------------
__global__ __launch_bounds__(256)
void pool_kernel(const float* __restrict__ x, float* __restrict__ out)
{
    const int br = blockIdx.x;
    const int b  = br >> 10;
    const int r  = br & 1023;
    const int i  = r >> 5;
    const int j  = r & 31;
    const int t00 = (i * 2) * 64 + (j * 2);
    const int tok[4] = {t00, t00 + 1, t00 + 64, t00 + 65};

    float l[4];
    #pragma unroll
    for (int k = 0; k < 4; k++) {
        const int t = b * N_TOK + tok[k];
        float s = 0.f;
        #pragma unroll
        for (int c = 0; c < NCHUNKS; c++) s += g_part[c][t];
        l[k] = s;
    }
    float mx = fmaxf(fmaxf(l[0], l[1]), fmaxf(l[2], l[3]));
    float e0 = __expf(l[0] - mx), e1 = __expf(l[1] - mx);
    float e2 = __expf(l[2] - mx), e3 = __expf(l[3] - mx);
    float inv = 1.f / (e0 + e1 + e2 + e3);
    float a0 = e0 * inv, a1 = e1 * inv, a2 = e2 * inv, a3 = e3 * inv;

    const size_t xb = (size_t)b * N_TOK * D_DIM;
    const float4* x0 = (const float4*)(x + xb + (size_t)tok[0] * D_DIM);
    const float4* x1 = (const float4*)(x + xb + (size_t)tok[1] * D_DIM);
    const float4* x2 = (const float4*)(x + xb + (size_t)tok[2] * D_DIM);
    const float4* x3 = (const float4*)(x + xb + (size_t)tok[3] * D_DIM);
    float4* o = (float4*)(out + (size_t)br * D_DIM);

    const int d = threadIdx.x;
    float4 v0 = x0[d], v1 = x1[d], v2 = x2[d], v3 = x3[d];
    float4 ov;
    ov.x = a0 * v0.x + a1 * v1.x + a2 * v2.x + a3 * v3.x;
    ov.y = a0 * v0.y + a1 * v1.y + a2 * v2.y + a3 * v3.y;
    ov.z = a0 * v0.z + a1 * v1.z + a2 * v2.z + a3 * v3.z;
    ov.w = a0 * v0.w + a1 * v1.w + a2 * v2.w + a3 * v3.w;
    o[d] = ov;
}

// ---------------------------------------------------------------------------
extern "C" void kernel_launch(void* const* d_in, const int* in_sizes, int n_in,
                              void* d_out, int out_size)
{
    const float* x  = (const float*)d_in[0];
    const float* W1 = (const float*)d_in[1];
    const float* b1 = (const float*)d_in[2];
    const float* W2 = (const float*)d_in[3];
    float* out = (float*)d_out;

    cudaFuncSetAttribute(logits_wmma_kernel,
                         cudaFuncAttributeMaxDynamicSharedMemorySize, SMEM_TOTAL);

    prep_x_kernel<<<(NTOK_TOTAL * (D_DIM / 4)) / 256, 256>>>(x);
    prep_w_kernel<<<D_DIM, 256>>>(W1);
    logits_wmma_kernel<<<dim3(NCHUNKS, NTOK_TOTAL / BM), 256, SMEM_TOTAL>>>(b1, W2);
    pool_kernel<<<B_SZ * (N_TOK / 4), 256>>>(x, out);
}

// round 9
// speedup vs baseline: 3.0982x; 1.4975x over previous
#include <cuda_runtime.h>
#include <cuda_fp16.h>
#include <mma.h>
#include <cstdint>

using namespace nvcuda;

// Shape: B=16, n=4096, D=1024. Tokens = 65536.
#define B_SZ   16
#define N_TOK  4096
#define D_DIM  1024
#define NTOK_TOTAL (B_SZ * N_TOK)

#define NCHUNKS 4          // 1024 / BN
#define BM 128
#define BN 256
#define BK 32
#define KSTEPS (D_DIM / BK)   // 32

#define XPAD 40            // fp16 elems per x-row in smem (32 + 8 pad)
#define WPAD 264           // fp16 elems per w-row in smem (256 + 8 pad)
#define EPAD 260           // f32 elems per epilogue row

// Scratch (__device__ globals: allocation-free rule)
__device__ float g_part[NCHUNKS][NTOK_TOTAL];
__device__ __half g_xf[(size_t)NTOK_TOTAL * D_DIM];    // fp16(x)
__device__ __half g_Whi[D_DIM * D_DIM];                // fp16 hi of W1 [k][e]
__device__ __half g_Wlo[D_DIM * D_DIM];                // fp16 lo of W1 [k][e]

// smem layout (bytes)
#define ST_XH 0                      // 128 * 80  = 10240
#define ST_WH 10240                  // 32 * 528  = 16896
#define ST_WL 27136                  // 16896
#define STAGE_B 44032
#define NSLOT 3
#define EP_BYTES (BM * EPAD * 4)     // 133120 (> 3*STAGE_B = 132096)
#define SM_B1 EP_BYTES               // 133120, 256 f32
#define SM_W2 (SM_B1 + 1024)
#define SMEM_TOTAL (SM_W2 + 1024)    // 135168

__device__ __forceinline__ uint32_t smem_u32(const void* p) {
    uint32_t a;
    asm("{ .reg .u64 t; cvta.to.shared.u64 t, %1; cvt.u32.u64 %0, t; }" : "=r"(a) : "l"(p));
    return a;
}
#define CP16(dst, src) \
    asm volatile("cp.async.cg.shared.global [%0], [%1], 16;" :: "r"(dst), "l"(src) : "memory")
#define CP_COMMIT() asm volatile("cp.async.commit_group;" ::: "memory")
#define CP_WAIT(n)  asm volatile("cp.async.wait_group %0;" :: "n"(n) : "memory")

// ---------------------------------------------------------------------------
// Prep: x -> fp16 (single), W1 -> fp16 hi/lo.
// ---------------------------------------------------------------------------
__global__ __launch_bounds__(256)
void prep_x_kernel(const float* __restrict__ x)
{
    const size_t i4 = (size_t)blockIdx.x * 256 + threadIdx.x;   // float4 index
    float4 v = ((const float4*)x)[i4];
    __half2 h0 = __floats2half2_rn(v.x, v.y);
    __half2 h1 = __floats2half2_rn(v.z, v.w);
    ((__half2*)g_xf)[i4 * 2]     = h0;
    ((__half2*)g_xf)[i4 * 2 + 1] = h1;
}

__global__ __launch_bounds__(256)
void prep_w_kernel(const float* __restrict__ W1)
{
    const int base = blockIdx.x * 1024 + threadIdx.x * 4;
    #pragma unroll
    for (int u = 0; u < 4; u++) {
        const int i = base + u;
        float w = W1[i];
        __half hi = __float2half(w);
        g_Whi[i] = hi;
        g_Wlo[i] = __float2half(w - __half2float(hi));
    }
}

// ---------------------------------------------------------------------------
// Kernel A: fp16x2 wmma logits GEMM, cp.async pipelined.
// Grid (4, 512): x = n-chunk (256 feats), y = m-tile (128 tokens).
// 8 warps, warp tile 64x64 (2m x 4n). K streamed in 32 stages of BK=32,
// 3 smem slots, pipeline depth 2. acc += x*Whi; acc += x*Wlo.
// ---------------------------------------------------------------------------
__global__ __launch_bounds__(256, 1)
void logits_wmma_kernel(const float* __restrict__ b1,
                        const float* __restrict__ W2)
{
    extern __shared__ char smem[];
    const uint32_t sb = smem_u32(smem);
    const int tid = threadIdx.x;
    const int wid = tid >> 5;
    const int n0  = blockIdx.x * BN;
    const int m0  = blockIdx.y * BM;

    float* s_b1 = (float*)(smem + SM_B1);
    float* s_w2 = (float*)(smem + SM_W2);
    if (tid < 256) { s_b1[tid] = b1[n0 + tid]; s_w2[tid] = W2[n0 + tid]; }

    // per-thread cp.async assignments
    // x: 128 rows x 32 fp16 = 64B/row = 4x16B chunks; 512 chunks, 2/thread
    const int xrow = tid >> 1;                  // 0..127
    const int xcc  = (tid & 1) * 2;             // chunk index base
    const size_t xg0 = (size_t)(m0 + xrow) * D_DIM + xcc * 8;
    const uint32_t xs0 = xrow * (XPAD * 2) + xcc * 16;

    auto issue_stage = [&](int kt, int slot) {
        const int k0 = kt * BK;
        const uint32_t s = sb + slot * STAGE_B;
        #pragma unroll
        for (int u = 0; u < 2; u++) {
            CP16(s + ST_XH + xs0 + u * 16, g_xf + xg0 + k0 + u * 8);
        }
        #pragma unroll
        for (int u = 0; u < 4; u++) {
            const int c  = tid * 4 + u;         // 0..1023
            const int r  = c >> 5;              // 0..31 (k row)
            const int cc = c & 31;              // 16B chunk in row
            const size_t g = (size_t)(k0 + r) * D_DIM + n0 + cc * 8;
            const uint32_t so = r * (WPAD * 2) + cc * 16;
            CP16(s + ST_WH + so, g_Whi + g);
            CP16(s + ST_WL + so, g_Wlo + g);
        }
        CP_COMMIT();
    };

    // warp tile: wm in {0,1} (64 rows), wn in {0..3} (64 cols)
    const int wm = wid & 1;
    const int wn = wid >> 1;

    wmma::fragment<wmma::accumulator, 16, 16, 16, float> acc[4][4];
    #pragma unroll
    for (int i = 0; i < 4; i++)
        #pragma unroll
        for (int j = 0; j < 4; j++) wmma::fill_fragment(acc[i][j], 0.f);

    issue_stage(0, 0);
    issue_stage(1, 1);

    #pragma unroll 2
    for (int kt = 0; kt < KSTEPS; kt++) {
        CP_WAIT(1);
        __syncthreads();
        if (kt + 2 < KSTEPS) issue_stage(kt + 2, (kt + 2) % NSLOT);
        else                 CP_COMMIT();

        const char* s = smem + (kt % NSLOT) * STAGE_B;
        const __half (*xh)[XPAD] = (const __half(*)[XPAD])(s + ST_XH);
        const __half (*wh)[WPAD] = (const __half(*)[WPAD])(s + ST_WH);
        const __half (*wl)[WPAD] = (const __half(*)[WPAD])(s + ST_WL);

        #pragma unroll
        for (int kk = 0; kk < BK; kk += 16) {
            wmma::fragment<wmma::matrix_a, 16, 16, 16, __half, wmma::row_major> ah[4];
            #pragma unroll
            for (int i = 0; i < 4; i++)
                wmma::load_matrix_sync(ah[i], &xh[wm * 64 + i * 16][kk], XPAD);
            #pragma unroll
            for (int j = 0; j < 4; j++) {
                wmma::fragment<wmma::matrix_b, 16, 16, 16, __half, wmma::row_major> bh, bl;
                wmma::load_matrix_sync(bh, &wh[kk][wn * 64 + j * 16], WPAD);
                wmma::load_matrix_sync(bl, &wl[kk][wn * 64 + j * 16], WPAD);
                #pragma unroll
                for (int i = 0; i < 4; i++) {
                    wmma::mma_sync(acc[i][j], ah[i], bh, acc[i][j]);
                    wmma::mma_sync(acc[i][j], ah[i], bl, acc[i][j]);
                }
            }
        }
        __syncthreads();
    }

    // epilogue: acc -> smem (aliases stage slots), reduce against b1/w2
    CP_WAIT(0);
    __syncthreads();
    float (*ep)[EPAD] = (float(*)[EPAD])smem;
    #pragma unroll
    for (int i = 0; i < 4; i++)
        #pragma unroll
        for (int j = 0; j < 4; j++)
            wmma::store_matrix_sync(&ep[wm * 64 + i * 16][wn * 64 + j * 16],
                                    acc[i][j], EPAD, wmma::mem_row_major);
    __syncthreads();

    const int row  = tid >> 1;
    const int half = tid & 1;
    float v = 0.f;
    #pragma unroll 8
    for (int c = 0; c < 128; c++) {
        const int e = half * 128 + c;
        float t = ep[row][e] + s_b1[e];
        t = fmaxf(t, 0.f);
        v = fmaf(t, s_w2[e], v);
    }
    v += __shfl_xor_sync(0xffffffffu, v, 1);
    if (half == 0) g_part[blockIdx.x][(size_t)m0 + row] = v;
}

// ---------------------------------------------------------------------------
// Kernel B: sum partials, 2x2 window softmax + weighted sum. (b2 shift-inv.)
// ---------------------------------------------------------------------------
__global__ __launch_bounds__(256)
void pool_kernel(const float* __restrict__ x, float* __restrict__ out)
{
    const int br = blockIdx.x;
    const int b  = br >> 10;
    const int r  = br & 1023;
    const int i  = r >> 5;
    const int j  = r & 31;
    const int t00 = (i * 2) * 64 + (j * 2);
    const int tok[4] = {t00, t00 + 1, t00 + 64, t00 + 65};

    float l[4];
    #pragma unroll
    for (int k = 0; k < 4; k++) {
        const int t = b * N_TOK + tok[k];
        float s = 0.f;
        #pragma unroll
        for (int c = 0; c < NCHUNKS; c++) s += g_part[c][t];
        l[k] = s;
    }
    float mx = fmaxf(fmaxf(l[0], l[1]), fmaxf(l[2], l[3]));
    float e0 = __expf(l[0] - mx), e1 = __expf(l[1] - mx);
    float e2 = __expf(l[2] - mx), e3 = __expf(l[3] - mx);
    float inv = 1.f / (e0 + e1 + e2 + e3);
    float a0 = e0 * inv, a1 = e1 * inv, a2 = e2 * inv, a3 = e3 * inv;

    const size_t xb = (size_t)b * N_TOK * D_DIM;
    const float4* x0 = (const float4*)(x + xb + (size_t)tok[0] * D_DIM);
    const float4* x1 = (const float4*)(x + xb + (size_t)tok[1] * D_DIM);
    const float4* x2 = (const float4*)(x + xb + (size_t)tok[2] * D_DIM);
    const float4* x3 = (const float4*)(x + xb + (size_t)tok[3] * D_DIM);
    float4* o = (float4*)(out + (size_t)br * D_DIM);

    const int d = threadIdx.x;
    float4 v0 = x0[d], v1 = x1[d], v2 = x2[d], v3 = x3[d];
    float4 ov;
    ov.x = a0 * v0.x + a1 * v1.x + a2 * v2.x + a3 * v3.x;
    ov.y = a0 * v0.y + a1 * v1.y + a2 * v2.y + a3 * v3.y;
    ov.z = a0 * v0.z + a1 * v1.z + a2 * v2.z + a3 * v3.z;
    ov.w = a0 * v0.w + a1 * v1.w + a2 * v2.w + a3 * v3.w;
    o[d] = ov;
}

// ---------------------------------------------------------------------------
extern "C" void kernel_launch(void* const* d_in, const int* in_sizes, int n_in,
                              void* d_out, int out_size)
{
    const float* x  = (const float*)d_in[0];
    const float* W1 = (const float*)d_in[1];
    const float* b1 = (const float*)d_in[2];
    const float* W2 = (const float*)d_in[3];
    float* out = (float*)d_out;

    cudaFuncSetAttribute(logits_wmma_kernel,
                         cudaFuncAttributeMaxDynamicSharedMemorySize, SMEM_TOTAL);

    prep_x_kernel<<<(NTOK_TOTAL * (D_DIM / 4)) / 256, 256>>>(x);
    prep_w_kernel<<<D_DIM, 256>>>(W1);
    logits_wmma_kernel<<<dim3(NCHUNKS, NTOK_TOTAL / BM), 256, SMEM_TOTAL>>>(b1, W2);
    pool_kernel<<<B_SZ * (N_TOK / 4), 256>>>(x, out);
}

// round 10
// speedup vs baseline: 4.8749x; 1.5734x over previous
#include <cuda_runtime.h>
#include <cuda_fp16.h>
#include <mma.h>
#include <cstdint>

using namespace nvcuda;

// Shape: B=16, n=4096, D=1024. Tokens = 65536.
#define B_SZ   16
#define N_TOK  4096
#define D_DIM  1024
#define NTOK_TOTAL (B_SZ * N_TOK)

#define NCHUNKS 4          // 1024 / BN
#define BM 128
#define BN 256
#define BK 32
#define KSTEPS (D_DIM / BK)   // 32

#define XPAD 40            // fp16 elems per x-row in smem (32 + 8 pad)
#define WPAD 264           // fp16 elems per w-row in smem (256 + 8 pad)
#define EPAD 260           // f32 elems per epilogue row

// Scratch (__device__ globals: allocation-free rule)
__device__ float g_part[NCHUNKS][NTOK_TOTAL];
__device__ __half g_xf[(size_t)NTOK_TOTAL * D_DIM];    // fp16(x)
__device__ __half g_Wh[D_DIM * D_DIM];                 // fp16(W1) [k][e]

// smem layout (bytes)
#define ST_XH 0                      // 128 * 80  = 10240
#define ST_WH 10240                  // 32 * 528  = 16896
#define STAGE_B 27136
#define NSLOT 3
#define EP_BYTES (BM * EPAD * 4)     // 133120 (> 3*STAGE_B = 81408)
#define SM_B1 EP_BYTES               // 133120, 256 f32
#define SM_W2 (SM_B1 + 1024)
#define SMEM_TOTAL (SM_W2 + 1024)    // 135168

__device__ __forceinline__ uint32_t smem_u32(const void* p) {
    uint32_t a;
    asm("{ .reg .u64 t; cvta.to.shared.u64 t, %1; cvt.u32.u64 %0, t; }" : "=r"(a) : "l"(p));
    return a;
}
#define CP16(dst, src) \
    asm volatile("cp.async.cg.shared.global [%0], [%1], 16;" :: "r"(dst), "l"(src) : "memory")
#define CP_COMMIT() asm volatile("cp.async.commit_group;" ::: "memory")
#define CP_WAIT(n)  asm volatile("cp.async.wait_group %0;" :: "n"(n) : "memory")

// ---------------------------------------------------------------------------
// Prep: x -> fp16, W1 -> fp16.
// ---------------------------------------------------------------------------
__global__ __launch_bounds__(256)
void prep_x_kernel(const float* __restrict__ x)
{
    const size_t i4 = (size_t)blockIdx.x * 256 + threadIdx.x;   // float4 index
    float4 v = ((const float4*)x)[i4];
    ((__half2*)g_xf)[i4 * 2]     = __floats2half2_rn(v.x, v.y);
    ((__half2*)g_xf)[i4 * 2 + 1] = __floats2half2_rn(v.z, v.w);
}

__global__ __launch_bounds__(256)
void prep_w_kernel(const float* __restrict__ W1)
{
    const size_t i4 = (size_t)blockIdx.x * 256 + threadIdx.x;
    float4 v = ((const float4*)W1)[i4];
    ((__half2*)g_Wh)[i4 * 2]     = __floats2half2_rn(v.x, v.y);
    ((__half2*)g_Wh)[i4 * 2 + 1] = __floats2half2_rn(v.z, v.w);
}

// ---------------------------------------------------------------------------
// Kernel A: fp16 wmma logits GEMM, cp.async pipelined.
// Grid (4, 512): x = n-chunk (256 feats), y = m-tile (128 tokens).
// 8 warps, warp tile 64x64 (2m x 4n). K streamed in 32 stages of BK=32,
// 3 smem slots, pipeline depth 2. acc += x*W (single product).
// ---------------------------------------------------------------------------
__global__ __launch_bounds__(256, 1)
void logits_wmma_kernel(const float* __restrict__ b1,
                        const float* __restrict__ W2)
{
    extern __shared__ char smem[];
    const uint32_t sb = smem_u32(smem);
    const int tid = threadIdx.x;
    const int wid = tid >> 5;
    const int n0  = blockIdx.x * BN;
    const int m0  = blockIdx.y * BM;

    float* s_b1 = (float*)(smem + SM_B1);
    float* s_w2 = (float*)(smem + SM_W2);
    if (tid < 256) { s_b1[tid] = b1[n0 + tid]; s_w2[tid] = W2[n0 + tid]; }

    // per-thread cp.async assignments
    // x: 128 rows x 32 fp16 = 64B/row = 4x16B chunks; 512 chunks, 2/thread
    const int xrow = tid >> 1;                  // 0..127
    const int xcc  = (tid & 1) * 2;             // chunk index base
    const size_t xg0 = (size_t)(m0 + xrow) * D_DIM + xcc * 8;
    const uint32_t xs0 = xrow * (XPAD * 2) + xcc * 16;

    auto issue_stage = [&](int kt, int slot) {
        const int k0 = kt * BK;
        const uint32_t s = sb + slot * STAGE_B;
        #pragma unroll
        for (int u = 0; u < 2; u++) {
            CP16(s + ST_XH + xs0 + u * 16, g_xf + xg0 + k0 + u * 8);
        }
        #pragma unroll
        for (int u = 0; u < 4; u++) {
            const int c  = tid * 4 + u;         // 0..1023
            const int r  = c >> 5;              // 0..31 (k row)
            const int cc = c & 31;              // 16B chunk in row
            const size_t g = (size_t)(k0 + r) * D_DIM + n0 + cc * 8;
            const uint32_t so = r * (WPAD * 2) + cc * 16;
            CP16(s + ST_WH + so, g_Wh + g);
        }
        CP_COMMIT();
    };

    // warp tile: wm in {0,1} (64 rows), wn in {0..3} (64 cols)
    const int wm = wid & 1;
    const int wn = wid >> 1;

    wmma::fragment<wmma::accumulator, 16, 16, 16, float> acc[4][4];
    #pragma unroll
    for (int i = 0; i < 4; i++)
        #pragma unroll
        for (int j = 0; j < 4; j++) wmma::fill_fragment(acc[i][j], 0.f);

    issue_stage(0, 0);
    issue_stage(1, 1);

    #pragma unroll 2
    for (int kt = 0; kt < KSTEPS; kt++) {
        CP_WAIT(1);
        __syncthreads();
        if (kt + 2 < KSTEPS) issue_stage(kt + 2, (kt + 2) % NSLOT);
        else                 CP_COMMIT();

        const char* s = smem + (kt % NSLOT) * STAGE_B;
        const __half (*xh)[XPAD] = (const __half(*)[XPAD])(s + ST_XH);
        const __half (*wh)[WPAD] = (const __half(*)[WPAD])(s + ST_WH);

        #pragma unroll
        for (int kk = 0; kk < BK; kk += 16) {
            wmma::fragment<wmma::matrix_a, 16, 16, 16, __half, wmma::row_major> ah[4];
            #pragma unroll
            for (int i = 0; i < 4; i++)
                wmma::load_matrix_sync(ah[i], &xh[wm * 64 + i * 16][kk], XPAD);
            #pragma unroll
            for (int j = 0; j < 4; j++) {
                wmma::fragment<wmma::matrix_b, 16, 16, 16, __half, wmma::row_major> bh;
                wmma::load_matrix_sync(bh, &wh[kk][wn * 64 + j * 16], WPAD);
                #pragma unroll
                for (int i = 0; i < 4; i++)
                    wmma::mma_sync(acc[i][j], ah[i], bh, acc[i][j]);
            }
        }
        __syncthreads();
    }

    // epilogue: acc -> smem (aliases stage slots), reduce against b1/w2
    CP_WAIT(0);
    __syncthreads();
    float (*ep)[EPAD] = (float(*)[EPAD])smem;
    #pragma unroll
    for (int i = 0; i < 4; i++)
        #pragma unroll
        for (int j = 0; j < 4; j++)
            wmma::store_matrix_sync(&ep[wm * 64 + i * 16][wn * 64 + j * 16],
                                    acc[i][j], EPAD, wmma::mem_row_major);
    __syncthreads();

    const int row  = tid >> 1;
    const int half = tid & 1;
    float v = 0.f;
    #pragma unroll 8
    for (int c = 0; c < 128; c++) {
        const int e = half * 128 + c;
        float t = ep[row][e] + s_b1[e];
        t = fmaxf(t, 0.f);
        v = fmaf(t, s_w2[e], v);
    }
    v += __shfl_xor_sync(0xffffffffu, v, 1);
    if (half == 0) g_part[blockIdx.x][(size_t)m0 + row] = v;
}

// ---------------------------------------------------------------------------
// Kernel B: sum partials, 2x2 window softmax + weighted sum. (b2 shift-inv.)
// ---------------------------------------------------------------------------
__global__ __launch_bounds__(256)
void pool_kernel(const float* __restrict__ x, float* __restrict__ out)
{
    const int br = blockIdx.x;
    const int b  = br >> 10;
    const int r  = br & 1023;
    const int i  = r >> 5;
    const int j  = r & 31;
    const int t00 = (i * 2) * 64 + (j * 2);
    const int tok[4] = {t00, t00 + 1, t00 + 64, t00 + 65};

    float l[4];
    #pragma unroll
    for (int k = 0; k < 4; k++) {
        const int t = b * N_TOK + tok[k];
        float s = 0.f;
        #pragma unroll
        for (int c = 0; c < NCHUNKS; c++) s += g_part[c][t];
        l[k] = s;
    }
    float mx = fmaxf(fmaxf(l[0], l[1]), fmaxf(l[2], l[3]));
    float e0 = __expf(l[0] - mx), e1 = __expf(l[1] - mx);
    float e2 = __expf(l[2] - mx), e3 = __expf(l[3] - mx);
    float inv = 1.f / (e0 + e1 + e2 + e3);
    float a0 = e0 * inv, a1 = e1 * inv, a2 = e2 * inv, a3 = e3 * inv;

    const size_t xb = (size_t)b * N_TOK * D_DIM;
    const float4* x0 = (const float4*)(x + xb + (size_t)tok[0] * D_DIM);
    const float4* x1 = (const float4*)(x + xb + (size_t)tok[1] * D_DIM);
    const float4* x2 = (const float4*)(x + xb + (size_t)tok[2] * D_DIM);
    const float4* x3 = (const float4*)(x + xb + (size_t)tok[3] * D_DIM);
    float4* o = (float4*)(out + (size_t)br * D_DIM);

    const int d = threadIdx.x;
    float4 v0 = x0[d], v1 = x1[d], v2 = x2[d], v3 = x3[d];
    float4 ov;
    ov.x = a0 * v0.x + a1 * v1.x + a2 * v2.x + a3 * v3.x;
    ov.y = a0 * v0.y + a1 * v1.y + a2 * v2.y + a3 * v3.y;
    ov.z = a0 * v0.z + a1 * v1.z + a2 * v2.z + a3 * v3.z;
    ov.w = a0 * v0.w + a1 * v1.w + a2 * v2.w + a3 * v3.w;
    o[d] = ov;
}

// ---------------------------------------------------------------------------
extern "C" void kernel_launch(void* const* d_in, const int* in_sizes, int n_in,
                              void* d_out, int out_size)
{
    const float* x  = (const float*)d_in[0];
    const float* W1 = (const float*)d_in[1];
    const float* b1 = (const float*)d_in[2];
    const float* W2 = (const float*)d_in[3];
    float* out = (float*)d_out;

    cudaFuncSetAttribute(logits_wmma_kernel,
                         cudaFuncAttributeMaxDynamicSharedMemorySize, SMEM_TOTAL);

    prep_x_kernel<<<(NTOK_TOTAL * (D_DIM / 4)) / 256, 256>>>(x);
    prep_w_kernel<<<(D_DIM * (D_DIM / 4)) / 256, 256>>>(W1);
    logits_wmma_kernel<<<dim3(NCHUNKS, NTOK_TOTAL / BM), 256, SMEM_TOTAL>>>(b1, W2);
    pool_kernel<<<B_SZ * (N_TOK / 4), 256>>>(x, out);
}